// round 1
// baseline (speedup 1.0000x reference)
#include <cuda_runtime.h>
#include <math_constants.h>

// Problem constants
#define BB 2
#define LL 2048
#define HH 1024
#define NHEAD 16
#define HD 64
#define ML (BB * LL)           // 4096 rows
#define SOFTMAX_SCALE (1.0f / 32.0f)   // 1/sqrt(WEIGHT_DIM=1024)
#define FMIN (-3.402823466e38f)

// Scratch (device globals: allocation-free rule)
__device__ float g_Q[BB * LL * HH];
__device__ float g_K[BB * LL * HH];
__device__ float g_V[BB * LL * HH];
__device__ float g_C[BB * LL * HH];

// ---------------------------------------------------------------------------
// Tiled SGEMM body: C[M=4096,1024] = A[4096,1024] @ W[1024,1024]
// BM=BN=64, BK=16, 256 threads, 4x4 microtile per thread.
// ---------------------------------------------------------------------------
__device__ __forceinline__ void gemm_body(const float* __restrict__ A,
                                          const float* __restrict__ W,
                                          float* __restrict__ C) {
    __shared__ float As[16][64];   // transposed: As[k][m]
    __shared__ float Bs[16][64];   // Bs[k][n]

    const int tid = threadIdx.x;
    const int tx = tid & 15;
    const int ty = tid >> 4;
    const int m0 = blockIdx.y * 64;
    const int n0 = blockIdx.x * 64;

    float acc[4][4] = {};

    for (int k0 = 0; k0 < 1024; k0 += 16) {
        // Load A tile 64x16 (one float4 per thread), store transposed
        {
            int r = tid >> 2;            // 0..63
            int c = (tid & 3) * 4;       // 0,4,8,12
            float4 a = *(const float4*)&A[(m0 + r) * 1024 + k0 + c];
            As[c + 0][r] = a.x;
            As[c + 1][r] = a.y;
            As[c + 2][r] = a.z;
            As[c + 3][r] = a.w;
        }
        // Load W tile 16x64 (one float4 per thread)
        {
            int r = tid >> 4;            // 0..15
            int c = (tid & 15) * 4;      // 0..60
            *(float4*)&Bs[r][c] = *(const float4*)&W[(k0 + r) * 1024 + n0 + c];
        }
        __syncthreads();

#pragma unroll
        for (int k = 0; k < 16; k++) {
            float4 a4 = *(const float4*)&As[k][ty * 4];
            float4 b4 = *(const float4*)&Bs[k][tx * 4];
            float av[4] = {a4.x, a4.y, a4.z, a4.w};
            float bv[4] = {b4.x, b4.y, b4.z, b4.w};
#pragma unroll
            for (int i = 0; i < 4; i++)
#pragma unroll
                for (int j = 0; j < 4; j++)
                    acc[i][j] += av[i] * bv[j];
        }
        __syncthreads();
    }

#pragma unroll
    for (int i = 0; i < 4; i++) {
        float4 o4 = make_float4(acc[i][0], acc[i][1], acc[i][2], acc[i][3]);
        *(float4*)&C[(m0 + ty * 4 + i) * 1024 + n0 + tx * 4] = o4;
    }
}

// QKV projection: blockIdx.z picks {Wq->g_Q, Wk->g_K, Wv->g_V}
__global__ void __launch_bounds__(256)
gemm_qkv(const float* __restrict__ X,
         const float* __restrict__ Wq,
         const float* __restrict__ Wk,
         const float* __restrict__ Wv) {
    const float* W = (blockIdx.z == 0) ? Wq : (blockIdx.z == 1) ? Wk : Wv;
    float* C = (blockIdx.z == 0) ? g_Q : (blockIdx.z == 1) ? g_K : g_V;
    gemm_body(X, W, C);
}

// Output projection: out = g_C @ Wo
__global__ void __launch_bounds__(256)
gemm_out(const float* __restrict__ Wo, float* __restrict__ out) {
    gemm_body(g_C, Wo, out);
}

// ---------------------------------------------------------------------------
// Flash-style attention. One block per (q_tile=64, head, batch).
// 256 threads, each owns a 4x4 tile of the 64x64 score block.
// Dynamic shared: Qs[64][64] ([d][q] transposed), Ks[64][64] ([d][k]
// transposed, reused as Ps[q][k]), Vs[64][64] ([k][d]), amk[64].
// ---------------------------------------------------------------------------
__global__ void __launch_bounds__(256)
attn_kernel(const float* __restrict__ am) {
    extern __shared__ float sm[];
    float* Qs  = sm;                 // [d][q]  (64x64)
    float* KPs = sm + 4096;          // K: [d][k], later P: [q][k]
    float* Vs  = sm + 8192;          // [k][d]
    float* amk = sm + 12288;         // [64]

    const int q0 = blockIdx.x * 64;
    const int h  = blockIdx.y;
    const int b  = blockIdx.z;

    const int tid = threadIdx.x;
    const int tx = tid & 15;
    const int ty = tid >> 4;

    // Load Q tile transposed: Qs[d][q]
#pragma unroll
    for (int t = 0; t < 4; t++) {
        int idx = tid + t * 256;          // 0..1023
        int r = idx >> 4;                 // q within tile, 0..63
        int c = (idx & 15) * 4;           // d offset, 0..60
        float4 a = *(const float4*)&g_Q[(b * LL + q0 + r) * HH + h * HD + c];
        Qs[(c + 0) * 64 + r] = a.x;
        Qs[(c + 1) * 64 + r] = a.y;
        Qs[(c + 2) * 64 + r] = a.z;
        Qs[(c + 3) * 64 + r] = a.w;
    }

    float am_q[4];
#pragma unroll
    for (int i = 0; i < 4; i++)
        am_q[i] = am[b * LL + q0 + ty * 4 + i];

    float m_i[4], l_i[4];
    float o[4][4] = {};
#pragma unroll
    for (int i = 0; i < 4; i++) { m_i[i] = -CUDART_INF_F; l_i[i] = 0.0f; }

    for (int k0 = 0; k0 <= q0; k0 += 64) {
        __syncthreads();   // previous PV done before overwriting tiles

        // Load K transposed and V natural
#pragma unroll
        for (int t = 0; t < 4; t++) {
            int idx = tid + t * 256;
            int r = idx >> 4;              // k within tile
            int c = (idx & 15) * 4;        // d offset
            float4 kk = *(const float4*)&g_K[(b * LL + k0 + r) * HH + h * HD + c];
            KPs[(c + 0) * 64 + r] = kk.x;
            KPs[(c + 1) * 64 + r] = kk.y;
            KPs[(c + 2) * 64 + r] = kk.z;
            KPs[(c + 3) * 64 + r] = kk.w;
            float4 vv = *(const float4*)&g_V[(b * LL + k0 + r) * HH + h * HD + c];
            *(float4*)&Vs[r * 64 + c] = vv;
        }
        if (tid < 64) amk[tid] = am[b * LL + k0 + tid];
        __syncthreads();

        // S = Q K^T  (per-thread 4x4)
        float s[4][4] = {};
#pragma unroll 8
        for (int dd = 0; dd < 64; dd++) {
            float4 q4 = *(const float4*)&Qs[dd * 64 + ty * 4];
            float4 k4 = *(const float4*)&KPs[dd * 64 + tx * 4];
            float qv[4] = {q4.x, q4.y, q4.z, q4.w};
            float kv[4] = {k4.x, k4.y, k4.z, k4.w};
#pragma unroll
            for (int i = 0; i < 4; i++)
#pragma unroll
                for (int j = 0; j < 4; j++)
                    s[i][j] += qv[i] * kv[j];
        }

        // Mask + scale (faithful to reference: add FMIN*mask, then /32)
        float am_k[4];
#pragma unroll
        for (int j = 0; j < 4; j++) am_k[j] = amk[tx * 4 + j];
#pragma unroll
        for (int i = 0; i < 4; i++) {
            int qi = q0 + ty * 4 + i;
#pragma unroll
            for (int j = 0; j < 4; j++) {
                int ki = k0 + tx * 4 + j;
                float fm = (ki > qi) ? 1.0f : 0.0f;
                float pm = 1.0f - am_q[i] * am_k[j];
                float maskv = fmaxf(fm, pm);
                s[i][j] = (s[i][j] + FMIN * maskv) * SOFTMAX_SCALE;
            }
        }

        // Online softmax: per-row reduce across the 16 tx threads
        float p[4][4];
#pragma unroll
        for (int i = 0; i < 4; i++) {
            float lm = fmaxf(fmaxf(s[i][0], s[i][1]), fmaxf(s[i][2], s[i][3]));
#pragma unroll
            for (int w = 8; w >= 1; w >>= 1)
                lm = fmaxf(lm, __shfl_xor_sync(0xffffffffu, lm, w));
            float new_m = fmaxf(m_i[i], lm);
            float corr = __expf(m_i[i] - new_m);
            float rs = 0.0f;
#pragma unroll
            for (int j = 0; j < 4; j++) {
                p[i][j] = __expf(s[i][j] - new_m);
                rs += p[i][j];
            }
#pragma unroll
            for (int w = 8; w >= 1; w >>= 1)
                rs += __shfl_xor_sync(0xffffffffu, rs, w);
            l_i[i] = l_i[i] * corr + rs;
            m_i[i] = new_m;
#pragma unroll
            for (int j = 0; j < 4; j++) o[i][j] *= corr;
        }

        __syncthreads();   // done reading K from KPs
        // Store P natural [q][k] as float4 rows (conflict-free)
#pragma unroll
        for (int i = 0; i < 4; i++) {
            float4 p4 = make_float4(p[i][0], p[i][1], p[i][2], p[i][3]);
            *(float4*)&KPs[(ty * 4 + i) * 64 + tx * 4] = p4;
        }
        __syncthreads();

        // O += P @ V
#pragma unroll 8
        for (int kk = 0; kk < 64; kk++) {
            float pv[4];
#pragma unroll
            for (int i = 0; i < 4; i++)
                pv[i] = KPs[(ty * 4 + i) * 64 + kk];   // broadcast loads
            float4 v4 = *(const float4*)&Vs[kk * 64 + tx * 4];
            float vv[4] = {v4.x, v4.y, v4.z, v4.w};
#pragma unroll
            for (int i = 0; i < 4; i++)
#pragma unroll
                for (int j = 0; j < 4; j++)
                    o[i][j] += pv[i] * vv[j];
        }
    }

    // Normalize and write ctx: g_C[b, q, h*64 + d]
#pragma unroll
    for (int i = 0; i < 4; i++) {
        float inv_l = 1.0f / l_i[i];
        float4 o4 = make_float4(o[i][0] * inv_l, o[i][1] * inv_l,
                                o[i][2] * inv_l, o[i][3] * inv_l);
        *(float4*)&g_C[(b * LL + q0 + ty * 4 + i) * HH + h * HD + tx * 4] = o4;
    }
}

// ---------------------------------------------------------------------------
extern "C" void kernel_launch(void* const* d_in, const int* in_sizes, int n_in,
                              void* d_out, int out_size) {
    const float* input = (const float*)d_in[0];
    const float* amask = (const float*)d_in[1];
    const float* wq    = (const float*)d_in[2];
    const float* wk    = (const float*)d_in[3];
    const float* wv    = (const float*)d_in[4];
    const float* wo    = (const float*)d_in[5];
    float* out = (float*)d_out;

    const int attn_smem = (3 * 4096 + 64) * (int)sizeof(float);   // 49408 B
    cudaFuncSetAttribute(attn_kernel,
                         cudaFuncAttributeMaxDynamicSharedMemorySize, 65536);

    // 1) QKV projections
    gemm_qkv<<<dim3(16, 64, 3), 256>>>(input, wq, wk, wv);
    // 2) Causal attention
    attn_kernel<<<dim3(LL / 64, NHEAD, BB), 256, attn_smem>>>(amask);
    // 3) Output projection
    gemm_out<<<dim3(16, 64, 1), 256>>>(wo, out);
}

// round 3
// speedup vs baseline: 3.2833x; 3.2833x over previous
#include <cuda_runtime.h>
#include <math_constants.h>

#define BB 2
#define LL 2048
#define HH 1024
#define NHEAD 16
#define HD 64
#define SOFTMAX_SCALE (1.0f / 32.0f)
#define FMIN (-3.402823466e38f)

// Scratch (device globals: allocation-free rule)
__device__ float g_Q[BB * LL * HH];
__device__ float g_K[BB * LL * HH];
__device__ float g_V[BB * LL * HH];
__device__ float g_C[BB * LL * HH];

// ---------------------------------------------------------------------------
// tf32 helpers
// ---------------------------------------------------------------------------
__device__ __forceinline__ unsigned f2tf(float x) {
    unsigned r;
    asm("cvt.rna.tf32.f32 %0, %1;" : "=r"(r) : "f"(x));
    return r;
}

__device__ __forceinline__ void mma_tf32(float* d, const unsigned* a, const unsigned* b) {
    asm volatile(
        "mma.sync.aligned.m16n8k8.row.col.f32.tf32.tf32.f32 "
        "{%0,%1,%2,%3}, {%4,%5,%6,%7}, {%8,%9}, {%0,%1,%2,%3};"
        : "+f"(d[0]), "+f"(d[1]), "+f"(d[2]), "+f"(d[3])
        : "r"(a[0]), "r"(a[1]), "r"(a[2]), "r"(a[3]), "r"(b[0]), "r"(b[1]));
}

// ---------------------------------------------------------------------------
// tf32 tensor-core SGEMM: C[4096,1024] = A[4096,1024] @ W[1024,1024]
// BM=BN=128, BK=16, 256 threads; warp grid 2(m) x 4(n); warp tile 64x32.
// ---------------------------------------------------------------------------
#define ASTR 20
#define BSTR 136

__device__ __forceinline__ void gemm_body(const float* __restrict__ A,
                                          const float* __restrict__ W,
                                          float* __restrict__ C) {
    __shared__ unsigned As[128 * ASTR];
    __shared__ unsigned Bs[16 * BSTR];

    const int tid = threadIdx.x;
    const int lane = tid & 31;
    const int wid = tid >> 5;
    const int wm = (wid >> 2) * 64;   // 0 or 64
    const int wn = (wid & 3) * 32;    // 0..96
    const int m0 = blockIdx.y * 128;
    const int n0 = blockIdx.x * 128;
    const int r0 = lane >> 2;         // 0..7
    const int j  = lane & 3;          // 0..3

    const float* Aptr = A + m0 * 1024;
    const float* Wptr = W + n0;

    float4 pa[2], pb[2];
#pragma unroll
    for (int t = 0; t < 2; t++) {
        int idx = tid + t * 256;
        pa[t] = *(const float4*)&Aptr[(idx >> 2) * 1024 + ((idx & 3) << 2)];
        pb[t] = *(const float4*)&Wptr[(idx >> 5) * 1024 + ((idx & 31) << 2)];
    }

    float acc[4][4][4];
#pragma unroll
    for (int mt = 0; mt < 4; mt++)
#pragma unroll
        for (int nt = 0; nt < 4; nt++)
#pragma unroll
            for (int i = 0; i < 4; i++) acc[mt][nt][i] = 0.0f;

    for (int k0 = 0; k0 < 1024; k0 += 16) {
#pragma unroll
        for (int t = 0; t < 2; t++) {
            int idx = tid + t * 256;
            int r = idx >> 2, c = (idx & 3) << 2;
            unsigned* p = &As[r * ASTR + c];
            p[0] = f2tf(pa[t].x); p[1] = f2tf(pa[t].y);
            p[2] = f2tf(pa[t].z); p[3] = f2tf(pa[t].w);
            int rb = idx >> 5, cb = (idx & 31) << 2;
            unsigned* q = &Bs[rb * BSTR + cb];
            q[0] = f2tf(pb[t].x); q[1] = f2tf(pb[t].y);
            q[2] = f2tf(pb[t].z); q[3] = f2tf(pb[t].w);
        }
        __syncthreads();

        if (k0 + 16 < 1024) {
#pragma unroll
            for (int t = 0; t < 2; t++) {
                int idx = tid + t * 256;
                pa[t] = *(const float4*)&Aptr[(idx >> 2) * 1024 + k0 + 16 + ((idx & 3) << 2)];
                pb[t] = *(const float4*)&Wptr[(k0 + 16 + (idx >> 5)) * 1024 + ((idx & 31) << 2)];
            }
        }

#pragma unroll
        for (int ks = 0; ks < 2; ks++) {
            const int k8 = ks * 8;
            unsigned af[4][4], bf[4][2];
#pragma unroll
            for (int mt = 0; mt < 4; mt++) {
                int bm = wm + mt * 16;
                af[mt][0] = As[(bm + r0) * ASTR + k8 + j];
                af[mt][1] = As[(bm + 8 + r0) * ASTR + k8 + j];
                af[mt][2] = As[(bm + r0) * ASTR + k8 + j + 4];
                af[mt][3] = As[(bm + 8 + r0) * ASTR + k8 + j + 4];
            }
#pragma unroll
            for (int nt = 0; nt < 4; nt++) {
                int bn = wn + nt * 8;
                bf[nt][0] = Bs[(k8 + j) * BSTR + bn + r0];
                bf[nt][1] = Bs[(k8 + 4 + j) * BSTR + bn + r0];
            }
#pragma unroll
            for (int mt = 0; mt < 4; mt++)
#pragma unroll
                for (int nt = 0; nt < 4; nt++)
                    mma_tf32(acc[mt][nt], af[mt], bf[nt]);
        }
        __syncthreads();
    }

#pragma unroll
    for (int mt = 0; mt < 4; mt++) {
        int rr = m0 + wm + mt * 16 + r0;
#pragma unroll
        for (int nt = 0; nt < 4; nt++) {
            int cc = n0 + wn + nt * 8 + (j << 1);
            *(float2*)&C[rr * 1024 + cc] = make_float2(acc[mt][nt][0], acc[mt][nt][1]);
            *(float2*)&C[(rr + 8) * 1024 + cc] = make_float2(acc[mt][nt][2], acc[mt][nt][3]);
        }
    }
}

__global__ void __launch_bounds__(256)
gemm_qkv(const float* __restrict__ X,
         const float* __restrict__ Wq,
         const float* __restrict__ Wk,
         const float* __restrict__ Wv) {
    const float* W = (blockIdx.z == 0) ? Wq : (blockIdx.z == 1) ? Wk : Wv;
    float* C = (blockIdx.z == 0) ? g_Q : (blockIdx.z == 1) ? g_K : g_V;
    gemm_body(X, W, C);
}

__global__ void __launch_bounds__(256)
gemm_out(const float* __restrict__ Wo, float* __restrict__ out) {
    gemm_body(g_C, Wo, out);
}

// ---------------------------------------------------------------------------
// Flash attention with tf32 mma. Block = 64 q rows x (head, batch).
// 128 threads (4 warps), each warp owns 16 q rows.
// ---------------------------------------------------------------------------
#define KSTR 68
#define VSTR 72

__global__ void __launch_bounds__(128)
attn_kernel(const float* __restrict__ am) {
    __shared__ unsigned Ks[64 * KSTR];
    __shared__ unsigned Vs[64 * VSTR];
    __shared__ float amk[64];

    const int tid = threadIdx.x;
    const int lane = tid & 31;
    const int w = tid >> 5;
    const int q0 = blockIdx.x * 64;
    const int h = blockIdx.y;
    const int b = blockIdx.z;
    const int bL = b * LL;
    const int r0 = lane >> 2;   // 0..7
    const int j = lane & 3;     // 0..3

    // Q fragments (held for entire loop): warp's 16 q rows x full d=64
    unsigned qa[8][4];
    const float* Qp = g_Q + (bL + q0 + w * 16) * HH + h * HD;
#pragma unroll
    for (int ks = 0; ks < 8; ks++) {
        qa[ks][0] = f2tf(Qp[r0 * HH + ks * 8 + j]);
        qa[ks][1] = f2tf(Qp[(r0 + 8) * HH + ks * 8 + j]);
        qa[ks][2] = f2tf(Qp[r0 * HH + ks * 8 + j + 4]);
        qa[ks][3] = f2tf(Qp[(r0 + 8) * HH + ks * 8 + j + 4]);
    }
    const float amq0 = am[bL + q0 + w * 16 + r0];
    const float amq1 = am[bL + q0 + w * 16 + r0 + 8];
    const int qi0 = q0 + w * 16 + r0;
    const int qi1 = qi0 + 8;

    float o[8][4] = {};
    float mr0 = -CUDART_INF_F, mr1 = -CUDART_INF_F;
    float l0 = 0.0f, l1 = 0.0f;

    for (int k0 = 0; k0 <= q0; k0 += 64) {
        __syncthreads();
        // Load K, V tiles: 64x64 floats each = 1024 float4 => 8 iters @128 thr
#pragma unroll
        for (int t = 0; t < 8; t++) {
            int idx = tid + t * 128;
            int r = idx >> 4, c = (idx & 15) << 2;
            float4 kk = *(const float4*)&g_K[(bL + k0 + r) * HH + h * HD + c];
            unsigned* kp = &Ks[r * KSTR + c];
            kp[0] = f2tf(kk.x); kp[1] = f2tf(kk.y); kp[2] = f2tf(kk.z); kp[3] = f2tf(kk.w);
            float4 vv = *(const float4*)&g_V[(bL + k0 + r) * HH + h * HD + c];
            unsigned* vp = &Vs[r * VSTR + c];
            vp[0] = f2tf(vv.x); vp[1] = f2tf(vv.y); vp[2] = f2tf(vv.z); vp[3] = f2tf(vv.w);
        }
        if (tid < 64) amk[tid] = am[bL + k0 + tid];
        __syncthreads();

        // S = Q K^T  (warp: 16 x 64)
        float s[8][4] = {};
#pragma unroll
        for (int ks = 0; ks < 8; ks++) {
#pragma unroll
            for (int nt = 0; nt < 8; nt++) {
                unsigned bf[2];
                bf[0] = Ks[(nt * 8 + r0) * KSTR + ks * 8 + j];
                bf[1] = Ks[(nt * 8 + r0) * KSTR + ks * 8 + j + 4];
                mma_tf32(s[nt], qa[ks], bf);
            }
        }

        // Mask (faithful: +FMIN*mask, then /32) + online softmax
        float nm0 = mr0, nm1 = mr1;
#pragma unroll
        for (int nt = 0; nt < 8; nt++) {
            int kc = k0 + nt * 8 + (j << 1);
            float ak0 = amk[nt * 8 + (j << 1)];
            float ak1 = amk[nt * 8 + (j << 1) + 1];
            float mk00 = fmaxf((kc > qi0) ? 1.f : 0.f, 1.f - amq0 * ak0);
            float mk01 = fmaxf((kc + 1 > qi0) ? 1.f : 0.f, 1.f - amq0 * ak1);
            float mk10 = fmaxf((kc > qi1) ? 1.f : 0.f, 1.f - amq1 * ak0);
            float mk11 = fmaxf((kc + 1 > qi1) ? 1.f : 0.f, 1.f - amq1 * ak1);
            s[nt][0] = (s[nt][0] + FMIN * mk00) * SOFTMAX_SCALE;
            s[nt][1] = (s[nt][1] + FMIN * mk01) * SOFTMAX_SCALE;
            s[nt][2] = (s[nt][2] + FMIN * mk10) * SOFTMAX_SCALE;
            s[nt][3] = (s[nt][3] + FMIN * mk11) * SOFTMAX_SCALE;
            nm0 = fmaxf(nm0, fmaxf(s[nt][0], s[nt][1]));
            nm1 = fmaxf(nm1, fmaxf(s[nt][2], s[nt][3]));
        }
        nm0 = fmaxf(nm0, __shfl_xor_sync(0xffffffffu, nm0, 1));
        nm0 = fmaxf(nm0, __shfl_xor_sync(0xffffffffu, nm0, 2));
        nm1 = fmaxf(nm1, __shfl_xor_sync(0xffffffffu, nm1, 1));
        nm1 = fmaxf(nm1, __shfl_xor_sync(0xffffffffu, nm1, 2));

        float corr0 = __expf(mr0 - nm0);
        float corr1 = __expf(mr1 - nm1);
        mr0 = nm0; mr1 = nm1;

        float rs0 = 0.0f, rs1 = 0.0f;
#pragma unroll
        for (int nt = 0; nt < 8; nt++) {
            s[nt][0] = __expf(s[nt][0] - nm0);
            s[nt][1] = __expf(s[nt][1] - nm0);
            s[nt][2] = __expf(s[nt][2] - nm1);
            s[nt][3] = __expf(s[nt][3] - nm1);
            rs0 += s[nt][0] + s[nt][1];
            rs1 += s[nt][2] + s[nt][3];
        }
        rs0 += __shfl_xor_sync(0xffffffffu, rs0, 1);
        rs0 += __shfl_xor_sync(0xffffffffu, rs0, 2);
        rs1 += __shfl_xor_sync(0xffffffffu, rs1, 1);
        rs1 += __shfl_xor_sync(0xffffffffu, rs1, 2);
        l0 = l0 * corr0 + rs0;
        l1 = l1 * corr1 + rs1;
#pragma unroll
        for (int dt = 0; dt < 8; dt++) {
            o[dt][0] *= corr0; o[dt][1] *= corr0;
            o[dt][2] *= corr1; o[dt][3] *= corr1;
        }

        // O += P @ V : permute P from C-fragment to A-fragment layout via shfl
#pragma unroll
        for (int nt = 0; nt < 8; nt++) {
            unsigned pc0 = f2tf(s[nt][0]), pc1 = f2tf(s[nt][1]);
            unsigned pc2 = f2tf(s[nt][2]), pc3 = f2tf(s[nt][3]);
            int src = (lane & ~3) | (j >> 1);
            int src2 = src + 2;
            unsigned x0 = __shfl_sync(0xffffffffu, pc0, src);
            unsigned x1 = __shfl_sync(0xffffffffu, pc1, src);
            unsigned y0 = __shfl_sync(0xffffffffu, pc2, src);
            unsigned y1 = __shfl_sync(0xffffffffu, pc3, src);
            unsigned x0b = __shfl_sync(0xffffffffu, pc0, src2);
            unsigned x1b = __shfl_sync(0xffffffffu, pc1, src2);
            unsigned y0b = __shfl_sync(0xffffffffu, pc2, src2);
            unsigned y1b = __shfl_sync(0xffffffffu, pc3, src2);
            unsigned af[4];
            af[0] = (lane & 1) ? x1 : x0;
            af[1] = (lane & 1) ? y1 : y0;
            af[2] = (lane & 1) ? x1b : x0b;
            af[3] = (lane & 1) ? y1b : y0b;
#pragma unroll
            for (int dt = 0; dt < 8; dt++) {
                unsigned bf[2];
                bf[0] = Vs[(nt * 8 + j) * VSTR + dt * 8 + r0];
                bf[1] = Vs[(nt * 8 + 4 + j) * VSTR + dt * 8 + r0];
                mma_tf32(o[dt], af, bf);
            }
        }
    }

    // Normalize and write ctx
    float inv0 = 1.0f / l0, inv1 = 1.0f / l1;
    float* Cp = g_C + (bL + q0 + w * 16) * HH + h * HD;
#pragma unroll
    for (int dt = 0; dt < 8; dt++) {
        int c = dt * 8 + (j << 1);
        *(float2*)&Cp[r0 * HH + c] = make_float2(o[dt][0] * inv0, o[dt][1] * inv0);
        *(float2*)&Cp[(r0 + 8) * HH + c] = make_float2(o[dt][2] * inv1, o[dt][3] * inv1);
    }
}

// ---------------------------------------------------------------------------
extern "C" void kernel_launch(void* const* d_in, const int* in_sizes, int n_in,
                              void* d_out, int out_size) {
    const float* input = (const float*)d_in[0];
    const float* amask = (const float*)d_in[1];
    const float* wq = (const float*)d_in[2];
    const float* wk = (const float*)d_in[3];
    const float* wv = (const float*)d_in[4];
    const float* wo = (const float*)d_in[5];
    float* out = (float*)d_out;

    gemm_qkv<<<dim3(8, 32, 3), 256>>>(input, wq, wk, wv);
    attn_kernel<<<dim3(LL / 64, NHEAD, BB), 128>>>(amask);
    gemm_out<<<dim3(8, 32), 256>>>(wo, out);
}

// round 4
// speedup vs baseline: 4.2384x; 1.2909x over previous
#include <cuda_runtime.h>
#include <math_constants.h>

#define BB 2
#define LL 2048
#define HH 1024
#define NHEAD 16
#define HD 64
#define SOFTMAX_SCALE (1.0f / 32.0f)
#define FMIN (-3.402823466e38f)

// Scratch (device globals: allocation-free rule)
__device__ float g_Q[BB * LL * HH];
__device__ float g_K[BB * LL * HH];
__device__ float g_V[BB * LL * HH];
__device__ float g_C[BB * LL * HH];
__device__ float g_X[BB * LL * HH];
__device__ float g_Wq[HH * HH];
__device__ float g_Wk[HH * HH];
__device__ float g_Wv[HH * HH];
__device__ float g_Wo[HH * HH];

// ---------------------------------------------------------------------------
// helpers
// ---------------------------------------------------------------------------
__device__ __forceinline__ unsigned f2tf(float x) {
    unsigned r;
    asm("cvt.rna.tf32.f32 %0, %1;" : "=r"(r) : "f"(x));
    return r;
}
__device__ __forceinline__ float frnd(float x) { return __uint_as_float(f2tf(x)); }

__device__ __forceinline__ void mma_tf32(float* d, const unsigned* a, const unsigned* b) {
    asm volatile(
        "mma.sync.aligned.m16n8k8.row.col.f32.tf32.tf32.f32 "
        "{%0,%1,%2,%3}, {%4,%5,%6,%7}, {%8,%9}, {%0,%1,%2,%3};"
        : "+f"(d[0]), "+f"(d[1]), "+f"(d[2]), "+f"(d[3])
        : "r"(a[0]), "r"(a[1]), "r"(a[2]), "r"(a[3]), "r"(b[0]), "r"(b[1]));
}

__device__ __forceinline__ void cp16(void* dst_smem, const void* src) {
    unsigned d = (unsigned)__cvta_generic_to_shared(dst_smem);
    asm volatile("cp.async.cg.shared.global [%0], [%1], 16;" :: "r"(d), "l"(src));
}
__device__ __forceinline__ void cp_commit() { asm volatile("cp.async.commit_group;"); }
__device__ __forceinline__ void cp_wait0() { asm volatile("cp.async.wait_group 0;"); }
__device__ __forceinline__ void cp_wait1() { asm volatile("cp.async.wait_group 1;"); }

// ---------------------------------------------------------------------------
// Pre-round inputs to tf32 (RNA) once.
// ---------------------------------------------------------------------------
__device__ __forceinline__ float4 rnd4(float4 v) {
    return make_float4(frnd(v.x), frnd(v.y), frnd(v.z), frnd(v.w));
}

__global__ void __launch_bounds__(256)
preconv_kernel(const float* __restrict__ x, const float* __restrict__ wq,
               const float* __restrict__ wk, const float* __restrict__ wv,
               const float* __restrict__ wo) {
    int i = blockIdx.x * blockDim.x + threadIdx.x;
    int stride = gridDim.x * blockDim.x;
    const int NX = BB * LL * HH / 4;
    const int NW = HH * HH / 4;
    for (int k = i; k < NX; k += stride)
        ((float4*)g_X)[k] = rnd4(((const float4*)x)[k]);
    for (int k = i; k < NW; k += stride) {
        ((float4*)g_Wq)[k] = rnd4(((const float4*)wq)[k]);
        ((float4*)g_Wk)[k] = rnd4(((const float4*)wk)[k]);
        ((float4*)g_Wv)[k] = rnd4(((const float4*)wv)[k]);
        ((float4*)g_Wo)[k] = rnd4(((const float4*)wo)[k]);
    }
}

// ---------------------------------------------------------------------------
// tf32 GEMM: C[4096,1024] = A @ W, BM=BN=128, BK=32, 3-stage cp.async.
// 256 threads, warp grid 2x4, warp tile 64x32. XOR-swizzled smem.
// Stage: A[128][32] floats (4096) + B[32][128] floats (4096) = 32KB.
// ---------------------------------------------------------------------------
#define GKT 32   // 1024/32

template <bool ROUND>
__device__ __forceinline__ void gemm_body(const float* __restrict__ A,
                                          const float* __restrict__ W,
                                          float* __restrict__ C) {
    extern __shared__ float sm[];

    const int tid = threadIdx.x;
    const int lane = tid & 31;
    const int wid = tid >> 5;
    const int wm = (wid >> 2) * 64;
    const int wn = (wid & 3) * 32;
    const int m0 = blockIdx.y * 128;
    const int n0 = blockIdx.x * 128;
    const int r0 = lane >> 2;
    const int j = lane & 3;

    const float* Ap = A + m0 * 1024;
    const float* Wp = W + n0;

    auto issue = [&](int it) {
        const int k0 = it * 32;
        float* As = sm + (it % 3) * 8192;
        float* Bs = As + 4096;
#pragma unroll
        for (int t = 0; t < 4; t++) {
            int id = tid + t * 256;
            int ra = id >> 3, ca = id & 7;
            cp16(&As[ra * 32 + ((ca ^ (ra & 7)) << 2)],
                 &Ap[ra * 1024 + k0 + (ca << 2)]);
            int rb = id >> 5, cb = id & 31;
            cp16(&Bs[rb * 128 + ((cb ^ ((rb & 3) << 1)) << 2)],
                 &Wp[(k0 + rb) * 1024 + (cb << 2)]);
        }
        cp_commit();
    };

    float acc[4][4][4];
#pragma unroll
    for (int mt = 0; mt < 4; mt++)
#pragma unroll
        for (int nt = 0; nt < 4; nt++)
#pragma unroll
            for (int i = 0; i < 4; i++) acc[mt][nt][i] = 0.0f;

    issue(0);
    issue(1);

    for (int it = 0; it < GKT; it++) {
        if (it == GKT - 1) cp_wait0(); else cp_wait1();
        __syncthreads();
        if (it + 2 < GKT) issue(it + 2);

        const float* As = sm + (it % 3) * 8192;
        const float* Bs = As + 4096;

#pragma unroll
        for (int kk = 0; kk < 4; kk++) {
            const int k8 = kk << 3;
            const int pA0 = (((kk << 1) ^ r0) << 2) + j;
            const int pA1 = ((((kk << 1) | 1) ^ r0) << 2) + j;
            unsigned af[4][4], bf[4][2];
#pragma unroll
            for (int mt = 0; mt < 4; mt++) {
                const float* base = As + (wm + mt * 16 + r0) * 32;
                af[mt][0] = __float_as_uint(base[pA0]);
                af[mt][1] = __float_as_uint(base[8 * 32 + pA0]);
                af[mt][2] = __float_as_uint(base[pA1]);
                af[mt][3] = __float_as_uint(base[8 * 32 + pA1]);
            }
#pragma unroll
            for (int nt = 0; nt < 4; nt++) {
                const int bn = wn + nt * 8;
                const int phys = (((((bn + r0) >> 2) ^ (j << 1)) << 2) | (r0 & 3));
                bf[nt][0] = __float_as_uint(Bs[(k8 + j) * 128 + phys]);
                bf[nt][1] = __float_as_uint(Bs[(k8 + 4 + j) * 128 + phys]);
            }
#pragma unroll
            for (int mt = 0; mt < 4; mt++)
#pragma unroll
                for (int nt = 0; nt < 4; nt++)
                    mma_tf32(acc[mt][nt], af[mt], bf[nt]);
        }
    }

#pragma unroll
    for (int mt = 0; mt < 4; mt++) {
        int rr = m0 + wm + mt * 16 + r0;
#pragma unroll
        for (int nt = 0; nt < 4; nt++) {
            int cc = n0 + wn + nt * 8 + (j << 1);
            if (ROUND) {
                *(float2*)&C[rr * 1024 + cc] =
                    make_float2(frnd(acc[mt][nt][0]), frnd(acc[mt][nt][1]));
                *(float2*)&C[(rr + 8) * 1024 + cc] =
                    make_float2(frnd(acc[mt][nt][2]), frnd(acc[mt][nt][3]));
            } else {
                *(float2*)&C[rr * 1024 + cc] =
                    make_float2(acc[mt][nt][0], acc[mt][nt][1]);
                *(float2*)&C[(rr + 8) * 1024 + cc] =
                    make_float2(acc[mt][nt][2], acc[mt][nt][3]);
            }
        }
    }
}

__global__ void __launch_bounds__(256, 2)
gemm_qkv() {
    const float* W = (blockIdx.z == 0) ? g_Wq : (blockIdx.z == 1) ? g_Wk : g_Wv;
    float* C = (blockIdx.z == 0) ? g_Q : (blockIdx.z == 1) ? g_K : g_V;
    gemm_body<true>(g_X, W, C);
}

__global__ void __launch_bounds__(256, 2)
gemm_out(float* __restrict__ out) {
    gemm_body<false>(g_C, g_Wo, out);
}

// ---------------------------------------------------------------------------
// Flash attention, tf32 mma, 2-stage cp.async K/V/mask pipeline.
// Block = 64 q rows x (head, batch), 128 threads (4 warps).
// Dyn smem: K[2][4096] | V[2][4096] | am[2][64]  (66048 B)
// ---------------------------------------------------------------------------
__global__ void __launch_bounds__(128, 3)
attn_kernel(const float* __restrict__ am) {
    extern __shared__ float sm[];

    const int tid = threadIdx.x;
    const int lane = tid & 31;
    const int w = tid >> 5;
    const int q0 = blockIdx.x * 64;
    const int h = blockIdx.y;
    const int b = blockIdx.z;
    const int bL = b * LL;
    const int r0 = lane >> 2;
    const int j = lane & 3;

    auto issue = [&](int ti) {
        const int k0 = ti * 64;
        const int s = ti & 1;
        float* Ks = sm + s * 4096;
        float* Vs = sm + 8192 + s * 4096;
        float* ams = sm + 16384 + s * 64;
#pragma unroll
        for (int t = 0; t < 8; t++) {
            int id = tid + t * 128;
            int r = id >> 4, c = id & 15;
            const float* gk = &g_K[(bL + k0 + r) * HH + h * HD + (c << 2)];
            const float* gv = &g_V[(bL + k0 + r) * HH + h * HD + (c << 2)];
            cp16(&Ks[r * 64 + ((c ^ (r & 7)) << 2)], gk);
            cp16(&Vs[r * 64 + ((c ^ ((r & 3) << 1)) << 2)], gv);
        }
        if (tid < 16) cp16(&ams[tid << 2], &am[bL + k0 + (tid << 2)]);
        cp_commit();
    };

    // Q fragments (pre-rounded in gmem -> raw bits are valid tf32)
    unsigned qa[8][4];
    const float* Qp = g_Q + (bL + q0 + w * 16) * HH + h * HD;
#pragma unroll
    for (int ks = 0; ks < 8; ks++) {
        qa[ks][0] = __float_as_uint(Qp[r0 * HH + ks * 8 + j]);
        qa[ks][1] = __float_as_uint(Qp[(r0 + 8) * HH + ks * 8 + j]);
        qa[ks][2] = __float_as_uint(Qp[r0 * HH + ks * 8 + j + 4]);
        qa[ks][3] = __float_as_uint(Qp[(r0 + 8) * HH + ks * 8 + j + 4]);
    }
    const float amq0 = am[bL + q0 + w * 16 + r0];
    const float amq1 = am[bL + q0 + w * 16 + r0 + 8];
    const int qi0 = q0 + w * 16 + r0;
    const int qi1 = qi0 + 8;

    float o[8][4] = {};
    float mr0 = -CUDART_INF_F, mr1 = -CUDART_INF_F;
    float l0 = 0.0f, l1 = 0.0f;

    const int ntiles = q0 / 64 + 1;
    issue(0);

    for (int ti = 0; ti < ntiles; ti++) {
        const int k0 = ti * 64;
        cp_wait0();
        __syncthreads();
        if (ti + 1 < ntiles) issue(ti + 1);

        const float* Ks = sm + (ti & 1) * 4096;
        const float* Vs = sm + 8192 + (ti & 1) * 4096;
        const float* ams = sm + 16384 + (ti & 1) * 64;

        // S = Q K^T
        float s[8][4] = {};
#pragma unroll
        for (int ks = 0; ks < 8; ks++) {
            const int pK0 = (((ks << 1) ^ r0) << 2) + j;
            const int pK1 = ((((ks << 1) | 1) ^ r0) << 2) + j;
#pragma unroll
            for (int nt = 0; nt < 8; nt++) {
                unsigned bf[2];
                bf[0] = __float_as_uint(Ks[(nt * 8 + r0) * 64 + pK0]);
                bf[1] = __float_as_uint(Ks[(nt * 8 + r0) * 64 + pK1]);
                mma_tf32(s[nt], qa[ks], bf);
            }
        }

        // Mask (faithful: +FMIN*mask, then /32) + online softmax
        float nm0 = mr0, nm1 = mr1;
#pragma unroll
        for (int nt = 0; nt < 8; nt++) {
            int kc = k0 + nt * 8 + (j << 1);
            float2 ak = *(const float2*)&ams[nt * 8 + (j << 1)];
            float mk00 = fmaxf((kc > qi0) ? 1.f : 0.f, 1.f - amq0 * ak.x);
            float mk01 = fmaxf((kc + 1 > qi0) ? 1.f : 0.f, 1.f - amq0 * ak.y);
            float mk10 = fmaxf((kc > qi1) ? 1.f : 0.f, 1.f - amq1 * ak.x);
            float mk11 = fmaxf((kc + 1 > qi1) ? 1.f : 0.f, 1.f - amq1 * ak.y);
            s[nt][0] = (s[nt][0] + FMIN * mk00) * SOFTMAX_SCALE;
            s[nt][1] = (s[nt][1] + FMIN * mk01) * SOFTMAX_SCALE;
            s[nt][2] = (s[nt][2] + FMIN * mk10) * SOFTMAX_SCALE;
            s[nt][3] = (s[nt][3] + FMIN * mk11) * SOFTMAX_SCALE;
            nm0 = fmaxf(nm0, fmaxf(s[nt][0], s[nt][1]));
            nm1 = fmaxf(nm1, fmaxf(s[nt][2], s[nt][3]));
        }
        nm0 = fmaxf(nm0, __shfl_xor_sync(0xffffffffu, nm0, 1));
        nm0 = fmaxf(nm0, __shfl_xor_sync(0xffffffffu, nm0, 2));
        nm1 = fmaxf(nm1, __shfl_xor_sync(0xffffffffu, nm1, 1));
        nm1 = fmaxf(nm1, __shfl_xor_sync(0xffffffffu, nm1, 2));

        float corr0 = __expf(mr0 - nm0);
        float corr1 = __expf(mr1 - nm1);
        mr0 = nm0; mr1 = nm1;

        float rs0 = 0.0f, rs1 = 0.0f;
#pragma unroll
        for (int nt = 0; nt < 8; nt++) {
            s[nt][0] = __expf(s[nt][0] - nm0);
            s[nt][1] = __expf(s[nt][1] - nm0);
            s[nt][2] = __expf(s[nt][2] - nm1);
            s[nt][3] = __expf(s[nt][3] - nm1);
            rs0 += s[nt][0] + s[nt][1];
            rs1 += s[nt][2] + s[nt][3];
        }
        rs0 += __shfl_xor_sync(0xffffffffu, rs0, 1);
        rs0 += __shfl_xor_sync(0xffffffffu, rs0, 2);
        rs1 += __shfl_xor_sync(0xffffffffu, rs1, 1);
        rs1 += __shfl_xor_sync(0xffffffffu, rs1, 2);
        l0 = l0 * corr0 + rs0;
        l1 = l1 * corr1 + rs1;
#pragma unroll
        for (int dt = 0; dt < 8; dt++) {
            o[dt][0] *= corr0; o[dt][1] *= corr0;
            o[dt][2] *= corr1; o[dt][3] *= corr1;
        }

        // O += P @ V : permute P (C-layout -> A-layout) via shfl
#pragma unroll
        for (int nt = 0; nt < 8; nt++) {
            unsigned pc0 = f2tf(s[nt][0]), pc1 = f2tf(s[nt][1]);
            unsigned pc2 = f2tf(s[nt][2]), pc3 = f2tf(s[nt][3]);
            int src = (lane & ~3) | (j >> 1);
            int src2 = src + 2;
            unsigned x0 = __shfl_sync(0xffffffffu, pc0, src);
            unsigned x1 = __shfl_sync(0xffffffffu, pc1, src);
            unsigned y0 = __shfl_sync(0xffffffffu, pc2, src);
            unsigned y1 = __shfl_sync(0xffffffffu, pc3, src);
            unsigned x0b = __shfl_sync(0xffffffffu, pc0, src2);
            unsigned x1b = __shfl_sync(0xffffffffu, pc1, src2);
            unsigned y0b = __shfl_sync(0xffffffffu, pc2, src2);
            unsigned y1b = __shfl_sync(0xffffffffu, pc3, src2);
            unsigned af[4];
            af[0] = (lane & 1) ? x1 : x0;
            af[1] = (lane & 1) ? y1 : y0;
            af[2] = (lane & 1) ? x1b : x0b;
            af[3] = (lane & 1) ? y1b : y0b;
#pragma unroll
            for (int dt = 0; dt < 8; dt++) {
                const int pv = ((((dt << 1) | (r0 >> 2)) ^ (j << 1)) << 2) | (r0 & 3);
                unsigned bf[2];
                bf[0] = __float_as_uint(Vs[(nt * 8 + j) * 64 + pv]);
                bf[1] = __float_as_uint(Vs[(nt * 8 + 4 + j) * 64 + pv]);
                mma_tf32(o[dt], af, bf);
            }
        }
    }

    // Normalize, round (next GEMM consumes as tf32), write ctx
    float inv0 = 1.0f / l0, inv1 = 1.0f / l1;
    float* Cp = g_C + (bL + q0 + w * 16) * HH + h * HD;
#pragma unroll
    for (int dt = 0; dt < 8; dt++) {
        int c = dt * 8 + (j << 1);
        *(float2*)&Cp[r0 * HH + c] =
            make_float2(frnd(o[dt][0] * inv0), frnd(o[dt][1] * inv0));
        *(float2*)&Cp[(r0 + 8) * HH + c] =
            make_float2(frnd(o[dt][2] * inv1), frnd(o[dt][3] * inv1));
    }
}

// ---------------------------------------------------------------------------
extern "C" void kernel_launch(void* const* d_in, const int* in_sizes, int n_in,
                              void* d_out, int out_size) {
    const float* input = (const float*)d_in[0];
    const float* amask = (const float*)d_in[1];
    const float* wq = (const float*)d_in[2];
    const float* wk = (const float*)d_in[3];
    const float* wv = (const float*)d_in[4];
    const float* wo = (const float*)d_in[5];
    float* out = (float*)d_out;

    static bool attr_done = false;
    if (!attr_done) {
        cudaFuncSetAttribute(gemm_qkv, cudaFuncAttributeMaxDynamicSharedMemorySize, 98304);
        cudaFuncSetAttribute(gemm_out, cudaFuncAttributeMaxDynamicSharedMemorySize, 98304);
        cudaFuncSetAttribute(attn_kernel, cudaFuncAttributeMaxDynamicSharedMemorySize, 66048);
        attr_done = true;
    }

    preconv_kernel<<<2048, 256>>>(input, wq, wk, wv, wo);
    gemm_qkv<<<dim3(8, 32, 3), 256, 98304>>>();
    attn_kernel<<<dim3(LL / 64, NHEAD, BB), 128, 66048>>>(amask);
    gemm_out<<<dim3(8, 32), 256, 98304>>>(out);
}